// round 10
// baseline (speedup 1.0000x reference)
#include <cuda_runtime.h>
#include <cuda_bf16.h>
#include <cstdint>

// ============================================================================
// Problem dims (fixed by the dataset)
// ============================================================================
#define N_TOK   4096      // B*S = 2*2048
#define V_DIM   32000
#define K_DIM   1024
#define EPSF    1e-5f
#define K0_CONST 12.8992199f   // ln(4/eps) = ln(400000)

// GEMM tiling — bf16 mma.sync m16n8k16 legacy pipe, warp-specialized:
// 8 consumer warps (2x4 grid, 64x32 warp tile) + 1 producer warp per CTA.
// grid (32,250), 2 CTAs/SM, 3-stage ring with mbarrier handshake
// (NO block-wide barrier in the mainloop).
#define BM      128
#define BN      128
#define BK      64                 // bf16 per K-chunk = 128 bytes/row
#define KITERS  (K_DIM / BK)       // 16
#define STAGES  3
#define THREADS 288                // 8 consumer warps + 1 producer warp

#define A_BYTES     (BM * BK * 2)            // 16384
#define B_BYTES     (BN * BK * 2)            // 16384
#define STAGE_BYTES (A_BYTES + B_BYTES)      // 32768
#define TABLE_BYTES ((BM + BN) * 2 * 4)      // 2048
#define SMEM_DYN    (1024 + STAGES * STAGE_BYTES + TABLE_BYTES)

// prep: 8 rows per 256-thread block (one warp per row)
#define PREP_ROWS_TOT (N_TOK + V_DIM)        // 36096
#define PREP_GRID     (PREP_ROWS_TOT / 8)    // 4512

// ============================================================================
// Device-global scratch (allocation-free rule: __device__ arrays)
// ============================================================================
__device__ __align__(128) __nv_bfloat16 g_xb[(size_t)N_TOK * K_DIM];   //  8 MB
__device__ __align__(128) __nv_bfloat16 g_yb[(size_t)V_DIM * K_DIM];   // 64 MB
__device__ float g_xsq[N_TOK];
__device__ float g_Ax[N_TOK];     // (1 - xsq) * 1e5
__device__ float g_ysq[V_DIM];
__device__ float g_By[V_DIM];     // (1 - ysq)

// ============================================================================
// PTX helpers (base-target: cp.async, ldmatrix, mma.sync, mbarrier)
// ============================================================================
__device__ __forceinline__ uint32_t smem_u32(const void* p) {
    uint32_t a;
    asm("{ .reg .u64 t; cvta.to.shared.u64 t, %1; cvt.u32.u64 %0, t; }"
        : "=r"(a) : "l"(p));
    return a;
}

#define CP_ASYNC16(saddr, gptr) \
    asm volatile("cp.async.cg.shared.global [%0], [%1], 16;" \
                 :: "r"(saddr), "l"(gptr) : "memory")

// .noinc: async completion DECREMENTS the preset count (init = #threads
// executing this). The default (inc) form is self-balancing and would never
// consume the init count -> deadlock (the exact R9 bug).
#define CP_ASYNC_MBAR_ARRIVE(mbar) \
    asm volatile("cp.async.mbarrier.arrive.noinc.shared::cta.b64 [%0];" \
                 :: "r"(mbar) : "memory")

#define MBAR_INIT(addr, cnt) \
    asm volatile("mbarrier.init.shared.b64 [%0], %1;" \
                 :: "r"(addr), "r"(cnt) : "memory")

#define MBAR_ARRIVE(addr) \
    asm volatile("mbarrier.arrive.shared.b64 _, [%0];" \
                 :: "r"(addr) : "memory")

__device__ __forceinline__ void mbar_wait(uint32_t mbar, uint32_t parity) {
    asm volatile(
        "{\n\t.reg .pred P1;\n"
        "LAB_W_%=:\n\t"
        "mbarrier.try_wait.parity.acquire.cta.shared::cta.b64 P1, [%0], %1, 0x989680;\n\t"
        "@P1 bra.uni LAB_D_%=;\n\t"
        "bra.uni LAB_W_%=;\n"
        "LAB_D_%=:\n\t}"
        :: "r"(mbar), "r"(parity) : "memory");
}

#define LDSM4(r0, r1, r2, r3, addr) \
    asm volatile("ldmatrix.sync.aligned.m8n8.x4.shared.b16 {%0,%1,%2,%3}, [%4];" \
                 : "=r"(r0), "=r"(r1), "=r"(r2), "=r"(r3) : "r"(addr))

#define MMA16816(c, a, b0, b1) \
    asm volatile("mma.sync.aligned.m16n8k16.row.col.f32.bf16.bf16.f32 " \
                 "{%0,%1,%2,%3}, {%4,%5,%6,%7}, {%8,%9}, {%0,%1,%2,%3};" \
                 : "+f"((c)[0]), "+f"((c)[1]), "+f"((c)[2]), "+f"((c)[3]) \
                 : "r"((a)[0]), "r"((a)[1]), "r"((a)[2]), "r"((a)[3]), \
                   "r"(b0), "r"(b1))

// ============================================================================
// Fused prep kernel: one warp per row, 8 rows per block, both tensors.
// ============================================================================
__global__ void __launch_bounds__(256) prep_all(const float* __restrict__ hidden,
                                                const float* __restrict__ weight) {
    const int lane = threadIdx.x & 31;
    const int w    = threadIdx.x >> 5;
    const int row  = blockIdx.x * 8 + w;

    const bool isx = (row < N_TOK);
    const int  r   = isx ? row : row - N_TOK;
    const float4* src = reinterpret_cast<const float4*>(isx ? hidden : weight)
                        + (size_t)r * 256;

    float4 v[8];
    #pragma unroll
    for (int j = 0; j < 8; ++j) v[j] = src[j * 32 + lane];

    float ss = 0.f;
    #pragma unroll
    for (int j = 0; j < 8; ++j)
        ss += fmaf(v[j].x, v[j].x, fmaf(v[j].y, v[j].y,
              fmaf(v[j].z, v[j].z, v[j].w * v[j].w)));
    #pragma unroll
    for (int o = 16; o; o >>= 1) ss += __shfl_xor_sync(0xFFFFFFFFu, ss, o);

    const float norm  = sqrtf(ss);
    const float scale = fminf((1.0f - EPSF) / (norm + 1e-10f), 1.0f);
    const float sq    = scale * scale * ss;

    if (lane == 0) {
        if (isx) { g_xsq[r] = sq; g_Ax[r] = (1.0f - sq) * 1e5f; }
        else     { g_ysq[r] = sq; g_By[r] = (1.0f - sq); }
    }

    uint2* dst = reinterpret_cast<uint2*>(isx ? g_xb : g_yb) + (size_t)r * 256;
    #pragma unroll
    for (int j = 0; j < 8; ++j) {
        __nv_bfloat162 b0 = __float22bfloat162_rn(
            make_float2(v[j].x * scale, v[j].y * scale));
        __nv_bfloat162 b1 = __float22bfloat162_rn(
            make_float2(v[j].z * scale, v[j].w * scale));
        uint2 u;
        u.x = *reinterpret_cast<uint32_t*>(&b0);
        u.y = *reinterpret_cast<uint32_t*>(&b1);
        dst[j * 32 + lane] = u;
    }
}

// ============================================================================
// Hyperbolic epilogue transform (fast closed form; guarded exact path)
// ============================================================================
__device__ __forceinline__ float hyp(float g, float xs, float An,
                                     float ys, float By) {
    const float d2 = fmaf(-2.0f, g, xs + ys);
    const float ab = An * By;       // (1-xs)(1-ys)/eps
    if (d2 > 0.25f && ab < 0.01f) {
        // -acosh(1 + 2*sqrt(d2)/(denom+eps)) ~= ab - ln(4/eps) - 0.5*ln(d2)
        return fmaf(-0.5f, __logf(d2), ab - K0_CONST);
    }
    const float dist  = sqrtf(fmaxf(d2, 0.0f));
    const float denom = (An * EPSF) * By + EPSF;
    const float arg   = fmaxf(1.0f + 2.0f * dist / denom, 1.0f + EPSF);
    return -acoshf(arg);
}

// ============================================================================
// Warp-specialized fused GEMM + epilogue.  grid (32, 250), 2 CTAs/SM.
// SMEM layout: [0..48) mbarriers (full[3]@0,8,16; empty[3]@24,32,40),
// tiles @ +1024, tables after tiles.
// ============================================================================
__global__ void __launch_bounds__(THREADS, 2) hyper_gemm(float* __restrict__ out) {
    extern __shared__ char smem[];
    const uint32_t sb    = smem_u32(smem);
    const uint32_t tiles = (sb + 1023) & ~1023u;
    char* smemc = smem + (tiles - sb);

    float* sXs  = reinterpret_cast<float*>(smemc + STAGES * STAGE_BYTES);
    float* sAn  = sXs + BM;
    float* sYsq = sAn + BM;
    float* sBy  = sYsq + BN;

    const int tid  = threadIdx.x;
    const int lane = tid & 31;
    const int wid  = tid >> 5;
    const int m0   = blockIdx.x * BM;
    const int v0   = blockIdx.y * BN;

    const uint32_t fullB  = sb;        // full[s]  = sb + s*8
    const uint32_t emptyB = sb + 24;   // empty[s] = sb + 24 + s*8

    if (tid == 0) {
        #pragma unroll
        for (int s = 0; s < STAGES; ++s) {
            MBAR_INIT(fullB  + s * 8, 32);    // producer .noinc async arrivals
            MBAR_INIT(emptyB + s * 8, 256);   // consumer thread arrivals
        }
    }
    // epilogue tables (consumer threads are exactly tid 0..255)
    if (tid < BM) { sXs[tid] = g_xsq[m0 + tid]; sAn[tid] = g_Ax[m0 + tid]; }
    else if (tid < BM + BN) {
        const int c = tid - BM; sYsq[c] = g_ysq[v0 + c]; sBy[c] = g_By[v0 + c];
    }
    __syncthreads();   // only block-wide barrier in the kernel

    if (wid == 8) {
        // ================= producer warp =================
        // per kt: 1024 A loads + 1024 B loads; 32 lanes -> 32+32 per lane.
        // mapping: t = 0..31, row = t*4 + (lane>>3), chunk = lane&7 (fixed).
        const int lr = lane >> 3;            // 0..3
        const int ch = lane & 7;             // fixed 16B chunk
        const uint32_t swe = (uint32_t)((ch ^ lr) * 16);        // row&7 = lr
        const uint32_t swo = (uint32_t)((ch ^ (lr + 4)) * 16);  // row&7 = lr+4
        const char* gA = reinterpret_cast<const char*>(g_xb)
                         + (size_t)m0 * (K_DIM * 2) + (size_t)ch * 16;
        const char* gB = reinterpret_cast<const char*>(g_yb)
                         + (size_t)v0 * (K_DIM * 2) + (size_t)ch * 16;

        int es = 0, ep = 0;                  // empty-cursor (starts at kt=3)
        #pragma unroll 1
        for (int kt = 0; kt < KITERS; ++kt) {
            const int s = kt % 3;
            if (kt >= STAGES) {
                mbar_wait(emptyB + es * 8, (uint32_t)ep);
                if (++es == STAGES) { es = 0; ep ^= 1; }
            }
            const uint32_t aSt = tiles + (uint32_t)s * STAGE_BYTES;
            const uint32_t bSt = aSt + A_BYTES;
            const size_t kOff = (size_t)kt * (BK * 2);
            #pragma unroll
            for (int t = 0; t < 32; ++t) {
                const int row = t * 4 + lr;
                const uint32_t sw = (t & 1) ? swo : swe;
                CP_ASYNC16(aSt + (uint32_t)(row * 128) + sw,
                           gA + (size_t)row * (K_DIM * 2) + kOff);
            }
            #pragma unroll
            for (int t = 0; t < 32; ++t) {
                const int row = t * 4 + lr;
                const uint32_t sw = (t & 1) ? swo : swe;
                CP_ASYNC16(bSt + (uint32_t)(row * 128) + sw,
                           gB + (size_t)row * (K_DIM * 2) + kOff);
            }
            CP_ASYNC_MBAR_ARRIVE(fullB + s * 8);
        }
        return;   // producer done; consumers handle the epilogue
    }

    // ================= consumer warps (0..7) =================
    const int wm = wid >> 2;            // 0..1  (M direction, 64 rows each)
    const int wn = wid & 3;             // 0..3  (N direction, 32 cols each)

    float acc[4][4][4] = {};

    // per-thread ldmatrix address components
    const int aRowB = wm * 64 + (lane & 15);                        // + i*16
    const int aChB  = lane >> 4;                                    // + 2*kk
    const int bRowB = wn * 32 + (lane & 7) + ((lane >> 4) << 3);    // + jp*16
    const int bChB  = (lane >> 3) & 1;                              // + 2*kk
    const int swz   = lane & 7;

    int cs = 0, cp_ = 0;                // full-cursor
    #pragma unroll 1
    for (int kt = 0; kt < KITERS; ++kt) {
        mbar_wait(fullB + cs * 8, (uint32_t)cp_);

        const uint32_t aSt = tiles + (uint32_t)cs * STAGE_BYTES;
        const uint32_t bSt = aSt + A_BYTES;

        #pragma unroll
        for (int kk = 0; kk < 4; ++kk) {         // 4 x k16 per 64-elt chunk
            uint32_t bf[2][4];
            #pragma unroll
            for (int jp = 0; jp < 2; ++jp) {
                const uint32_t addr = bSt
                    + (uint32_t)((bRowB + jp * 16) * 128)
                    + (uint32_t)((((kk * 2 + bChB) ^ swz) * 16));
                LDSM4(bf[jp][0], bf[jp][1], bf[jp][2], bf[jp][3], addr);
            }
            uint32_t af[2][4];
            {
                const uint32_t addr = aSt
                    + (uint32_t)(aRowB * 128)
                    + (uint32_t)((((kk * 2 + aChB) ^ swz) * 16));
                LDSM4(af[0][0], af[0][1], af[0][2], af[0][3], addr);
            }
            #pragma unroll
            for (int i = 0; i < 4; ++i) {
                if (i < 3) {
                    const uint32_t addr = aSt
                        + (uint32_t)((aRowB + (i + 1) * 16) * 128)
                        + (uint32_t)((((kk * 2 + aChB) ^ swz) * 16));
                    LDSM4(af[(i + 1) & 1][0], af[(i + 1) & 1][1],
                          af[(i + 1) & 1][2], af[(i + 1) & 1][3], addr);
                }
                #pragma unroll
                for (int j = 0; j < 4; ++j)
                    MMA16816(acc[i][j], af[i & 1],
                             bf[j >> 1][(j & 1) * 2],
                             bf[j >> 1][(j & 1) * 2 + 1]);
            }
        }

        MBAR_ARRIVE(emptyB + cs * 8);   // this thread done reading stage cs
        if (++cs == STAGES) { cs = 0; cp_ ^= 1; }
    }

    // ---------------- epilogue: transform + store ----------------
    const int rBase = wm * 64 + (lane >> 2);        // + i*16 (+8)
    const int cBase = wn * 32 + (lane & 3) * 2;     // + j*8

    #pragma unroll
    for (int i = 0; i < 4; ++i) {
        const int ra = rBase + i * 16;
        const int rb = ra + 8;
        const float xsa = sXs[ra], Ana = sAn[ra];
        const float xsb = sXs[rb], Anb = sAn[rb];
        float* outA = out + (size_t)(m0 + ra) * V_DIM + v0;
        float* outB = out + (size_t)(m0 + rb) * V_DIM + v0;
        #pragma unroll
        for (int j = 0; j < 4; ++j) {
            const int lc = cBase + j * 8;
            const float ys0 = sYsq[lc],     By0 = sBy[lc];
            const float ys1 = sYsq[lc + 1], By1 = sBy[lc + 1];
            float2 pa, pb;
            pa.x = hyp(acc[i][j][0], xsa, Ana, ys0, By0);
            pa.y = hyp(acc[i][j][1], xsa, Ana, ys1, By1);
            pb.x = hyp(acc[i][j][2], xsb, Anb, ys0, By0);
            pb.y = hyp(acc[i][j][3], xsb, Anb, ys1, By1);
            *reinterpret_cast<float2*>(outA + lc) = pa;
            *reinterpret_cast<float2*>(outB + lc) = pb;
        }
    }
}

// ============================================================================
// Launch
// ============================================================================
extern "C" void kernel_launch(void* const* d_in, const int* in_sizes, int n_in,
                              void* d_out, int out_size) {
    const float* hidden = (const float*)d_in[0];
    const float* weight = (const float*)d_in[1];
    float* out = (float*)d_out;

    prep_all<<<PREP_GRID, 256>>>(hidden, weight);

    cudaFuncSetAttribute(hyper_gemm,
                         cudaFuncAttributeMaxDynamicSharedMemorySize, SMEM_DYN);
    dim3 grid(N_TOK / BM, V_DIM / BN);   // m-fastest: A L2-resident, B streamed once
    hyper_gemm<<<grid, THREADS, SMEM_DYN>>>(out);
}